// round 16
// baseline (speedup 1.0000x reference)
#include <cuda_runtime.h>
#include <cuda_fp16.h>
#include <stdint.h>

// ---------------- problem dims ----------------
#define T_DIM   512
#define B_DIM   256
#define F_DIM   258
#define M_ROWS  (T_DIM * B_DIM)   // 131072
#define K0      256
#define H_DIM   1024
#define NCHUNK  64                 // scan chunks
#define CLEN    (T_DIM / NCHUNK)   // 8
#define MTILES  (M_ROWS / 128)     // 1024

// ---------------- scratch (static device globals; allocation-free) ------------
__device__ __align__(16) __half g_A[(size_t)M_ROWS * H_DIM];
__device__ __align__(16) __half g_B[(size_t)M_ROWS * H_DIM];
__device__ __align__(16) __half g_W0[(size_t)H_DIM * K0];
__device__ __align__(16) __half g_W1[(size_t)H_DIM * H_DIM];
__device__ __align__(16) __half g_W2[(size_t)H_DIM * H_DIM];
__device__ float g_net[M_ROWS];
__device__ float g_part[NCHUNK * B_DIM];
__device__ int   g_cnt[2][MTILES];   // layer-done counters (zero-init; reset at end)

// ---------------- portable PTX helpers (compute_103-safe) ----------------
__device__ __forceinline__ uint32_t smem_u32(const void* p) {
    uint32_t a;
    asm("{ .reg .u64 t; cvta.to.shared.u64 t, %1; cvt.u32.u64 %0, t; }"
        : "=r"(a) : "l"(p));
    return a;
}

__device__ __forceinline__ void cpa16(uint32_t dst, const void* src) {
    asm volatile("cp.async.cg.shared.global [%0], [%1], 16;"
                 :: "r"(dst), "l"(src));
}
#define CP_COMMIT() asm volatile("cp.async.commit_group;" ::: "memory")
#define CP_WAIT1()  asm volatile("cp.async.wait_group 1;" ::: "memory")

#define LDSM_X4(r0, r1, r2, r3, addr) \
    asm volatile("ldmatrix.sync.aligned.m8n8.x4.shared.b16 {%0,%1,%2,%3}, [%4];" \
                 : "=r"(r0), "=r"(r1), "=r"(r2), "=r"(r3) : "r"(addr))

__device__ __forceinline__ void mma_f16(float* c, const uint32_t* a, const uint32_t* b) {
    asm volatile(
        "mma.sync.aligned.m16n8k16.row.col.f32.f16.f16.f32 "
        "{%0,%1,%2,%3}, {%4,%5,%6,%7}, {%8,%9}, {%0,%1,%2,%3};"
        : "+f"(c[0]), "+f"(c[1]), "+f"(c[2]), "+f"(c[3])
        : "r"(a[0]), "r"(a[1]), "r"(a[2]), "r"(a[3]), "r"(b[0]), "r"(b[1]));
}

// swizzle: 128B rows, 16B chunk index ^= (row & 7). Apply to FINAL offset.
#define SWZ(off)    ((off) ^ ((((off) >> 7) & 7) << 4))
// swizzle for 256B rows (epilogue staging): chunk ^= (row & 7)
#define SWZ256(off) ((off) ^ ((((off) >> 8) & 7) << 4))

// ---------------- kernel 1: fused prep --------------------------------------
#define NB_PACK  32768                 // 1024 elems/block (4 per thread)
#define NB_W0    256
#define NB_W1    1024
#define NB_W2    1024
#define NB_NET   256
#define NB_PREP  (NB_PACK + NB_W0 + NB_W1 + NB_W2 + NB_NET)

__global__ void __launch_bounds__(256)
prep_kernel(const float* __restrict__ u,
            const float* __restrict__ W0, const float* __restrict__ W1,
            const float* __restrict__ W2,
            const float* __restrict__ pb, const float* __restrict__ b3) {
    __shared__ __half s[32][33];
    int bid = blockIdx.x;
    const int tid = threadIdx.x;

    if (bid < NB_PACK) {
        // pack: 4 elems/thread (float2 x2 reads, 8B write)
        long idx = ((long)bid * 256 + tid) * 4;
        int m = (int)(idx >> 8);
        int k = (int)(idx & 255);
        const float* src = u + (size_t)m * F_DIM + 2 + k;
        float2 v0 = *(const float2*)(src);
        float2 v1 = *(const float2*)(src + 2);
        __half2 h0 = __floats2half2_rn(v0.x, v0.y);
        __half2 h1 = __floats2half2_rn(v1.x, v1.y);
        uint2 pk = make_uint2(*(uint32_t*)&h0, *(uint32_t*)&h1);
        *(uint2*)(g_A + (size_t)m * K0 + k) = pk;
        return;
    }
    bid -= NB_PACK;

    if (bid < NB_W0 + NB_W1 + NB_W2) {
        const float* W; __half* Wt; int K, N, t;
        if (bid < NB_W0)              { W = W0; Wt = g_W0; K = K0;    N = H_DIM; t = bid; }
        else if (bid < NB_W0 + NB_W1) { W = W1; Wt = g_W1; K = H_DIM; N = H_DIM; t = bid - NB_W0; }
        else                          { W = W2; Wt = g_W2; K = H_DIM; N = H_DIM; t = bid - NB_W0 - NB_W1; }
        const int tn = t % (N >> 5), tk = t / (N >> 5);
        const int tx = tid & 31, ty = tid >> 5;        // 32 x 8
        const int k0 = tk * 32, n0 = tn * 32;
#pragma unroll
        for (int i = 0; i < 4; i++)
            s[ty + 8 * i][tx] = __float2half(W[(size_t)(k0 + ty + 8 * i) * N + n0 + tx]);
        __syncthreads();
#pragma unroll
        for (int i = 0; i < 4; i++)
            Wt[(size_t)(n0 + ty + 8 * i) * K + k0 + tx] = s[tx][ty + 8 * i];
        return;
    }
    bid -= NB_W0 + NB_W1 + NB_W2;

    int m = (bid * 256 + tid) * 2;
    const float bb = *pb, bv = *b3;
    g_net[m]     = bv + bb * u[(size_t)m * F_DIM + 1];
    g_net[m + 1] = bv + bb * u[(size_t)(m + 1) * F_DIM + 1];
}

// ---------------- kernel 2: fused 3-layer fp16 mma.sync GEMM ----------------
// grid (8, 3072): blockIdx.y>>10 = layer, &1023 = M-tile. In-order dispatch
// guarantees producers of a tile are dispatched before its consumers; flag
// counters (8 N-tiles per M-tile) give per-tile release/acquire handoff, so
// layer boundaries pipeline with no drain/launch gap (CUTLASS split-k pattern).
// Mainloop/epilogues identical to R14. 2 CTAs/SM.
#define STAGE  32768
#define OFF_B  16384
#define NSTG   3
#define GEMM_SMEM (NSTG * STAGE)

__global__ void __launch_bounds__(128, 2)
gemm3_kernel(const float* __restrict__ b0, const float* __restrict__ b1,
             const float* __restrict__ b2,
             const float* __restrict__ w3, float* __restrict__ net) {
    extern __shared__ __align__(1024) char smem[];
    const uint32_t sb = smem_u32(smem);

    const int tid = threadIdx.x;
    const int wid = tid >> 5;        // 0..3
    const int lid = tid & 31;
    const int wr  = wid >> 1;        // 0..1  (M)
    const int wc  = wid & 1;         // 0..1  (N)

    const int ly  = (int)blockIdx.y >> 10;      // layer 0..2
    const int my  = (int)blockIdx.y & 1023;     // M-tile
    const int n0  = blockIdx.x * 128;
    const int m0  = my * 128;

    const __half* X; const __half* Wt; const float* bias; __half* Y; int K;
    if (ly == 0)      { X = g_A; Wt = g_W0; bias = b0; Y = g_B; K = K0;    }
    else if (ly == 1) { X = g_B; Wt = g_W1; bias = b1; Y = g_A; K = H_DIM; }
    else              { X = g_A; Wt = g_W2; bias = b2; Y = g_B; K = H_DIM; }

    // ---- dependency wait: producers of this M-tile (8 N-tiles) done ----
    if (ly != 0) {
        if (tid == 0) {
            while (atomicAdd(&g_cnt[ly - 1][my], 0) < 8) __nanosleep(64);
            __threadfence();                    // acquire
        }
        __syncthreads();                        // propagate to all threads
    }

    // ---- cp.async per-thread constants ----
    const int ldr = tid >> 3;                       // 0..15
    const int ldc = tid & 7;                        // 16B chunk
    const uint32_t dst_base =
        (uint32_t)(ldr * 128 + ((ldc ^ (ldr & 7)) * 16));   // +it*2048
    const size_t kb = (size_t)K * 2;                // row bytes in global

    const char* gA = (const char*)(X  + (size_t)m0 * K) + ldr * kb + ldc * 16;
    const char* gB = (const char*)(Wt + (size_t)n0 * K) + ldr * kb + ldc * 16;

    // ---- ldmatrix per-lane UNswizzled base offsets (swizzle applied at use) ----
    uint32_t abase[4];
#pragma unroll
    for (int mt = 0; mt < 4; mt++) {
        int r = wr * 64 + mt * 16 + (lid & 15);
        abase[mt] = (uint32_t)(r * 128 + (lid >> 4) * 16);
    }
    uint32_t bbase[4];
#pragma unroll
    for (int ntp = 0; ntp < 4; ntp++) {
        int r = wc * 64 + ntp * 16 + (lid & 7) + ((lid >> 4) & 1) * 8;
        bbase[ntp] = (uint32_t)(r * 128 + ((lid >> 3) & 1) * 16);
    }

    float acc[4][8][4];
#pragma unroll
    for (int mt = 0; mt < 4; mt++)
#pragma unroll
        for (int nt = 0; nt < 8; nt++)
#pragma unroll
            for (int q = 0; q < 4; q++) acc[mt][nt][q] = 0.0f;

    const int nkc = K >> 6;          // K / 64

    auto issue = [&](int kc, int st) {
        uint32_t d = sb + st * STAGE + dst_base;
        size_t  go = (size_t)kc * 128;             // 64 fp16 = 128 bytes
#pragma unroll
        for (int it = 0; it < 8; it++) {
            uint32_t dd = d + it * 2048;
            size_t   gg = go + (size_t)it * 16 * kb;
            cpa16(dd,         gA + gg);
            cpa16(dd + OFF_B, gB + gg);
        }
        CP_COMMIT();
    };

    issue(0, 0);
    if (nkc > 1) issue(1, 1); else CP_COMMIT();

    int st = 0;                      // stage of kc
    for (int kc = 0; kc < nkc; kc++) {
        CP_WAIT1();                  // group kc complete (own) ...
        __syncthreads();             // ... CTA-visible; stage (kc+2)%3 free

        if (kc + 2 < nkc) {
            int st2 = st + 2; if (st2 >= NSTG) st2 -= NSTG;
            issue(kc + 2, st2);
        } else {
            CP_COMMIT();             // keep group count consistent
        }

        const uint32_t s0 = sb + st * STAGE;
#pragma unroll
        for (int ks = 0; ks < 4; ks++) {
            uint32_t ah[4][4], bh[4][4];
#pragma unroll
            for (int mt = 0; mt < 4; mt++) {
                uint32_t rel = SWZ(abase[mt] + ks * 32);
                LDSM_X4(ah[mt][0], ah[mt][1], ah[mt][2], ah[mt][3], s0 + rel);
            }
#pragma unroll
            for (int ntp = 0; ntp < 4; ntp++) {
                uint32_t rel = SWZ(bbase[ntp] + ks * 32);
                LDSM_X4(bh[ntp][0], bh[ntp][1], bh[ntp][2], bh[ntp][3],
                        s0 + OFF_B + rel);
            }
#pragma unroll
            for (int mt = 0; mt < 4; mt++) {
#pragma unroll
                for (int nt = 0; nt < 8; nt++) {
                    mma_f16(acc[mt][nt], ah[mt], &bh[nt >> 1][(nt & 1) * 2]);
                }
            }
        }
        if (++st == NSTG) st = 0;
    }

    const int erow = wr * 64 + (lid >> 2);          // row within 128-tile
    const int ecol = wc * 64 + 2 * (lid & 3);       // col within 128-tile

    if (ly != 2) {
        // ---- epilogue A: bias + relu -> fp16, staged via smem for
        //      coalesced 16B global stores ----
        __syncthreads();             // all mainloop smem reads done; reuse stage 0
#pragma unroll
        for (int mt = 0; mt < 4; mt++) {
#pragma unroll
            for (int nt = 0; nt < 8; nt++) {
                const int col = ecol + nt * 8;
                const float bv0 = __ldg(&bias[n0 + col]);
                const float bv1 = __ldg(&bias[n0 + col + 1]);
#pragma unroll
                for (int h = 0; h < 2; h++) {
                    const int row = erow + mt * 16 + h * 8;
                    float v0 = fmaxf(acc[mt][nt][2 * h]     + bv0, 0.0f);
                    float v1 = fmaxf(acc[mt][nt][2 * h + 1] + bv1, 0.0f);
                    __half2 hv = __floats2half2_rn(v0, v1);
                    uint32_t off = SWZ256((uint32_t)(row * 256 + col * 2));
                    *(uint32_t*)(smem + off) = *(uint32_t*)&hv;
                }
            }
        }
        __syncthreads();
        // coalesced copy-out: 8 rows/iter (4 warps x 2 rows), 16B per lane
        const int orow = tid >> 4;        // 0..7
        const int ochk = tid & 15;        // 16B chunk in 256B row
#pragma unroll
        for (int it = 0; it < 16; it++) {
            const int row = it * 8 + orow;
            uint32_t off = SWZ256((uint32_t)(row * 256 + ochk * 16));
            uint4 v = *(const uint4*)(smem + off);
            *(uint4*)((char*)(Y + (size_t)(m0 + row) * H_DIM + n0) + ochk * 16) = v;
        }
        // ---- release: this N-tile of M-tile my is done ----
        __syncthreads();
        if (tid == 0) { __threadfence(); atomicAdd(&g_cnt[ly][my], 1); }
    } else {
        // ---- epilogue B: fused final layer: net += relu(acc+bias) . w3 ----
#pragma unroll
        for (int mt = 0; mt < 4; mt++) {
#pragma unroll
            for (int h = 0; h < 2; h++) {
                float rs = 0.0f;
#pragma unroll
                for (int nt = 0; nt < 8; nt++) {
                    const int col = n0 + ecol + nt * 8;
                    float v0 = fmaxf(acc[mt][nt][2 * h]     + __ldg(&bias[col]),     0.0f);
                    float v1 = fmaxf(acc[mt][nt][2 * h + 1] + __ldg(&bias[col + 1]), 0.0f);
                    rs = fmaf(v0, __ldg(&w3[col]),     rs);
                    rs = fmaf(v1, __ldg(&w3[col + 1]), rs);
                }
                rs += __shfl_xor_sync(0xffffffffu, rs, 1);
                rs += __shfl_xor_sync(0xffffffffu, rs, 2);
                if ((lid & 3) == 0) {
                    const int row = m0 + erow + mt * 16 + h * 8;
                    atomicAdd(&net[row], rs);
                }
            }
        }
    }
}

// ---------------- scan: chunked parallel decomposition (2 kernels) ----------
// part: per-chunk recurrence from 0 (64 blocks, fully parallel)
__global__ void scan_part_kernel(const float* __restrict__ pa) {
    const int c = blockIdx.x;         // 0..NCHUNK-1
    const int b = threadIdx.x;        // 0..255
    const float a = *pa;
    float y = 0.0f;
    const float* p = g_net + (size_t)c * CLEN * B_DIM + b;
#pragma unroll
    for (int j = 0; j < CLEN; j++) y = fmaf(a, y, p[j * B_DIM]);
    g_part[c * B_DIM + b] = y;
}

// out: each block computes its OWN ystart, replays its chunk, and resets its
// slice of the dependency counters for the next graph replay.
__global__ void scan_out_kernel(const float* __restrict__ u,
                                const float* __restrict__ pa,
                                float* __restrict__ out) {
    const int c = blockIdx.x;
    const int b = threadIdx.x;

    // reset dependency counters (2048 ints = 64 blocks x 32)
    if (b < 32) ((int*)g_cnt)[c * 32 + b] = 0;

    const float a = *pa;
    float aL = a;                     // a^CLEN by squaring (CLEN = 8)
    aL = aL * aL; aL = aL * aL; aL = aL * aL;

    // preload needed partials (coalesced, independent loads)
    float part[NCHUNK];
#pragma unroll
    for (int i = 0; i < NCHUNK; i++)
        part[i] = (i < c) ? g_part[i * B_DIM + b] : 0.0f;

    // local fixup chain: ystart_c (same op order as sequential fixup)
    float y = u[(size_t)b * F_DIM];   // y0 = u[0, b, 0]
#pragma unroll
    for (int i = 0; i < NCHUNK; i++)
        if (i < c) y = fmaf(aL, y, part[i]);

    if (c == 0) out[b] = y;           // out[0, b] = y0
    const float* p = g_net + (size_t)c * CLEN * B_DIM + b;
    float* o = out + (size_t)(c * CLEN + 1) * B_DIM + b;
#pragma unroll
    for (int j = 0; j < CLEN; j++) {
        y = fmaf(a, y, p[j * B_DIM]);
        o[j * B_DIM] = y;
    }
}

// ---------------- launch ----------------
extern "C" void kernel_launch(void* const* d_in, const int* in_sizes, int n_in,
                              void* d_out, int out_size) {
    const float* u  = (const float*)d_in[0];
    const float* a  = (const float*)d_in[1];
    const float* b  = (const float*)d_in[2];
    const float* W0 = (const float*)d_in[3];
    const float* b0 = (const float*)d_in[4];
    const float* W1 = (const float*)d_in[5];
    const float* b1 = (const float*)d_in[6];
    const float* W2 = (const float*)d_in[7];
    const float* b2 = (const float*)d_in[8];
    const float* W3 = (const float*)d_in[9];
    const float* b3 = (const float*)d_in[10];
    float* out = (float*)d_out;

    void* pNet;
    cudaGetSymbolAddress(&pNet, g_net);

    cudaFuncSetAttribute(gemm3_kernel, cudaFuncAttributeMaxDynamicSharedMemorySize,
                         GEMM_SMEM);

    // 1. fused prep: pack + weight transposes + net init
    prep_kernel<<<NB_PREP, 256>>>(u, W0, W1, W2, b, b3);

    // 2. all three GEMM layers in ONE launch; per-M-tile flag handoff
    dim3 grid(H_DIM / 128, 3 * MTILES);
    gemm3_kernel<<<grid, 128, GEMM_SMEM>>>(b0, b1, b2, W3, (float*)pNet);

    // 3. parallel scan (2 launches; per-block local fixup + counter reset)
    scan_part_kernel<<<NCHUNK, B_DIM>>>(a);
    scan_out_kernel<<<NCHUNK, B_DIM>>>(u, a, out);
}

// round 17
// speedup vs baseline: 1.0269x; 1.0269x over previous
#include <cuda_runtime.h>
#include <cuda_fp16.h>
#include <stdint.h>

// ---------------- problem dims ----------------
#define T_DIM   512
#define B_DIM   256
#define F_DIM   258
#define M_ROWS  (T_DIM * B_DIM)   // 131072
#define K0      256
#define H_DIM   1024
#define NCHUNK  64                 // scan chunks
#define CLEN    (T_DIM / NCHUNK)   // 8

// ---------------- scratch (static device globals; allocation-free) ------------
__device__ __align__(16) __half g_A[(size_t)M_ROWS * H_DIM];
__device__ __align__(16) __half g_B[(size_t)M_ROWS * H_DIM];
__device__ __align__(16) __half g_W0[(size_t)H_DIM * K0];
__device__ __align__(16) __half g_W1[(size_t)H_DIM * H_DIM];
__device__ __align__(16) __half g_W2[(size_t)H_DIM * H_DIM];
__device__ float g_net[M_ROWS];
__device__ float g_part[NCHUNK * B_DIM];
__device__ int   g_scnt;             // scan part-completion counter

// ---------------- portable PTX helpers (compute_103-safe) ----------------
__device__ __forceinline__ uint32_t smem_u32(const void* p) {
    uint32_t a;
    asm("{ .reg .u64 t; cvta.to.shared.u64 t, %1; cvt.u32.u64 %0, t; }"
        : "=r"(a) : "l"(p));
    return a;
}

__device__ __forceinline__ void cpa16(uint32_t dst, const void* src) {
    asm volatile("cp.async.cg.shared.global [%0], [%1], 16;"
                 :: "r"(dst), "l"(src));
}
#define CP_COMMIT() asm volatile("cp.async.commit_group;" ::: "memory")
#define CP_WAIT1()  asm volatile("cp.async.wait_group 1;" ::: "memory")

#define LDSM_X4(r0, r1, r2, r3, addr) \
    asm volatile("ldmatrix.sync.aligned.m8n8.x4.shared.b16 {%0,%1,%2,%3}, [%4];" \
                 : "=r"(r0), "=r"(r1), "=r"(r2), "=r"(r3) : "r"(addr))

__device__ __forceinline__ void mma_f16(float* c, const uint32_t* a, const uint32_t* b) {
    asm volatile(
        "mma.sync.aligned.m16n8k16.row.col.f32.f16.f16.f32 "
        "{%0,%1,%2,%3}, {%4,%5,%6,%7}, {%8,%9}, {%0,%1,%2,%3};"
        : "+f"(c[0]), "+f"(c[1]), "+f"(c[2]), "+f"(c[3])
        : "r"(a[0]), "r"(a[1]), "r"(a[2]), "r"(a[3]), "r"(b[0]), "r"(b[1]));
}

// swizzle: 128B rows, 16B chunk index ^= (row & 7). Apply to FINAL offset.
#define SWZ(off)    ((off) ^ ((((off) >> 7) & 7) << 4))
// swizzle for 256B rows (epilogue staging): chunk ^= (row & 7)
#define SWZ256(off) ((off) ^ ((((off) >> 8) & 7) << 4))

// ---------------- kernel 1: fused prep --------------------------------------
#define NB_PACK  32768                 // 1024 elems/block (4 per thread)
#define NB_W0    256
#define NB_W1    1024
#define NB_W2    1024
#define NB_NET   256
#define NB_PREP  (NB_PACK + NB_W0 + NB_W1 + NB_W2 + NB_NET)

__global__ void __launch_bounds__(256)
prep_kernel(const float* __restrict__ u,
            const float* __restrict__ W0, const float* __restrict__ W1,
            const float* __restrict__ W2,
            const float* __restrict__ pb, const float* __restrict__ b3) {
    __shared__ __half s[32][33];
    int bid = blockIdx.x;
    const int tid = threadIdx.x;

    if (bid < NB_PACK) {
        // pack: 4 elems/thread (float2 x2 reads, 8B write)
        long idx = ((long)bid * 256 + tid) * 4;
        int m = (int)(idx >> 8);
        int k = (int)(idx & 255);
        const float* src = u + (size_t)m * F_DIM + 2 + k;
        float2 v0 = *(const float2*)(src);
        float2 v1 = *(const float2*)(src + 2);
        __half2 h0 = __floats2half2_rn(v0.x, v0.y);
        __half2 h1 = __floats2half2_rn(v1.x, v1.y);
        uint2 pk = make_uint2(*(uint32_t*)&h0, *(uint32_t*)&h1);
        *(uint2*)(g_A + (size_t)m * K0 + k) = pk;
        return;
    }
    bid -= NB_PACK;

    if (bid < NB_W0 + NB_W1 + NB_W2) {
        const float* W; __half* Wt; int K, N, t;
        if (bid < NB_W0)              { W = W0; Wt = g_W0; K = K0;    N = H_DIM; t = bid; }
        else if (bid < NB_W0 + NB_W1) { W = W1; Wt = g_W1; K = H_DIM; N = H_DIM; t = bid - NB_W0; }
        else                          { W = W2; Wt = g_W2; K = H_DIM; N = H_DIM; t = bid - NB_W0 - NB_W1; }
        const int tn = t % (N >> 5), tk = t / (N >> 5);
        const int tx = tid & 31, ty = tid >> 5;        // 32 x 8
        const int k0 = tk * 32, n0 = tn * 32;
#pragma unroll
        for (int i = 0; i < 4; i++)
            s[ty + 8 * i][tx] = __float2half(W[(size_t)(k0 + ty + 8 * i) * N + n0 + tx]);
        __syncthreads();
#pragma unroll
        for (int i = 0; i < 4; i++)
            Wt[(size_t)(n0 + ty + 8 * i) * K + k0 + tx] = s[tx][ty + 8 * i];
        return;
    }
    bid -= NB_W0 + NB_W1 + NB_W2;

    if (bid == 0 && tid == 0) g_scnt = 0;   // reset scan counter for this replay
    int m = (bid * 256 + tid) * 2;
    const float bb = *pb, bv = *b3;
    g_net[m]     = bv + bb * u[(size_t)m * F_DIM + 1];
    g_net[m + 1] = bv + bb * u[(size_t)(m + 1) * F_DIM + 1];
}

// ---------------- kernel 3: fp16 mma.sync GEMM -----------------------------
// CTA tile 128x128, K-chunk 64, 128 threads (4 warps as 2Mx2N, warp 64x64).
// 3-stage cp.async pipeline. Epilogue A staged through smem for coalesced
// 16B global stores. 2 CTAs/SM (register file exactly full).
// If w3 != nullptr: fused final layer into epilogue (no Y store).
#define STAGE  32768
#define OFF_B  16384
#define NSTG   3
#define GEMM_SMEM (NSTG * STAGE)

__global__ void __launch_bounds__(128, 2)
gemm_kernel(const __half* __restrict__ X, const __half* __restrict__ Wt,
            const float* __restrict__ bias, __half* __restrict__ Y,
            int K, int N,
            const float* __restrict__ w3, float* __restrict__ net) {
    extern __shared__ __align__(1024) char smem[];
    const uint32_t sb = smem_u32(smem);

    const int tid = threadIdx.x;
    const int wid = tid >> 5;        // 0..3
    const int lid = tid & 31;
    const int wr  = wid >> 1;        // 0..1  (M)
    const int wc  = wid & 1;         // 0..1  (N)
    const int n0  = blockIdx.x * 128;   // N fastest -> co-resident N-tiles share A
    const int m0  = blockIdx.y * 128;

    // ---- cp.async per-thread constants ----
    const int ldr = tid >> 3;                       // 0..15
    const int ldc = tid & 7;                        // 16B chunk
    const uint32_t dst_base =
        (uint32_t)(ldr * 128 + ((ldc ^ (ldr & 7)) * 16));   // +it*2048
    const size_t kb = (size_t)K * 2;                // row bytes in global

    const char* gA = (const char*)(X  + (size_t)m0 * K) + ldr * kb + ldc * 16;
    const char* gB = (const char*)(Wt + (size_t)n0 * K) + ldr * kb + ldc * 16;

    // ---- ldmatrix per-lane UNswizzled base offsets (swizzle applied at use) ----
    uint32_t abase[4];
#pragma unroll
    for (int mt = 0; mt < 4; mt++) {
        int r = wr * 64 + mt * 16 + (lid & 15);
        abase[mt] = (uint32_t)(r * 128 + (lid >> 4) * 16);
    }
    uint32_t bbase[4];
#pragma unroll
    for (int ntp = 0; ntp < 4; ntp++) {
        int r = wc * 64 + ntp * 16 + (lid & 7) + ((lid >> 4) & 1) * 8;
        bbase[ntp] = (uint32_t)(r * 128 + ((lid >> 3) & 1) * 16);
    }

    float acc[4][8][4];
#pragma unroll
    for (int mt = 0; mt < 4; mt++)
#pragma unroll
        for (int nt = 0; nt < 8; nt++)
#pragma unroll
            for (int q = 0; q < 4; q++) acc[mt][nt][q] = 0.0f;

    const int nkc = K >> 6;          // K / 64

    auto issue = [&](int kc, int st) {
        uint32_t d = sb + st * STAGE + dst_base;
        size_t  go = (size_t)kc * 128;             // 64 fp16 = 128 bytes
#pragma unroll
        for (int it = 0; it < 8; it++) {
            uint32_t dd = d + it * 2048;
            size_t   gg = go + (size_t)it * 16 * kb;
            cpa16(dd,         gA + gg);
            cpa16(dd + OFF_B, gB + gg);
        }
        CP_COMMIT();
    };

    issue(0, 0);
    if (nkc > 1) issue(1, 1); else CP_COMMIT();

    int st = 0;                      // stage of kc
    for (int kc = 0; kc < nkc; kc++) {
        CP_WAIT1();                  // group kc complete (own) ...
        __syncthreads();             // ... CTA-visible; stage (kc+2)%3 free

        if (kc + 2 < nkc) {
            int st2 = st + 2; if (st2 >= NSTG) st2 -= NSTG;
            issue(kc + 2, st2);
        } else {
            CP_COMMIT();             // keep group count consistent
        }

        const uint32_t s0 = sb + st * STAGE;
#pragma unroll
        for (int ks = 0; ks < 4; ks++) {
            uint32_t ah[4][4], bh[4][4];
#pragma unroll
            for (int mt = 0; mt < 4; mt++) {
                uint32_t rel = SWZ(abase[mt] + ks * 32);
                LDSM_X4(ah[mt][0], ah[mt][1], ah[mt][2], ah[mt][3], s0 + rel);
            }
#pragma unroll
            for (int ntp = 0; ntp < 4; ntp++) {
                uint32_t rel = SWZ(bbase[ntp] + ks * 32);
                LDSM_X4(bh[ntp][0], bh[ntp][1], bh[ntp][2], bh[ntp][3],
                        s0 + OFF_B + rel);
            }
#pragma unroll
            for (int mt = 0; mt < 4; mt++) {
#pragma unroll
                for (int nt = 0; nt < 8; nt++) {
                    mma_f16(acc[mt][nt], ah[mt], &bh[nt >> 1][(nt & 1) * 2]);
                }
            }
        }
        if (++st == NSTG) st = 0;
    }

    const int erow = wr * 64 + (lid >> 2);          // row within 128-tile
    const int ecol = wc * 64 + 2 * (lid & 3);       // col within 128-tile

    if (w3 == nullptr) {
        // ---- epilogue A: bias + relu -> fp16, staged via smem for
        //      coalesced 16B global stores ----
        __syncthreads();             // all mainloop smem reads done; reuse stage 0
#pragma unroll
        for (int mt = 0; mt < 4; mt++) {
#pragma unroll
            for (int nt = 0; nt < 8; nt++) {
                const int col = ecol + nt * 8;
                const float bv0 = __ldg(&bias[n0 + col]);
                const float bv1 = __ldg(&bias[n0 + col + 1]);
#pragma unroll
                for (int h = 0; h < 2; h++) {
                    const int row = erow + mt * 16 + h * 8;
                    float v0 = fmaxf(acc[mt][nt][2 * h]     + bv0, 0.0f);
                    float v1 = fmaxf(acc[mt][nt][2 * h + 1] + bv1, 0.0f);
                    __half2 hv = __floats2half2_rn(v0, v1);
                    uint32_t off = SWZ256((uint32_t)(row * 256 + col * 2));
                    *(uint32_t*)(smem + off) = *(uint32_t*)&hv;
                }
            }
        }
        __syncthreads();
        // coalesced copy-out: 8 rows/iter (4 warps x 2 rows), 16B per lane
        const int orow = tid >> 4;        // 0..7
        const int ochk = tid & 15;        // 16B chunk in 256B row
#pragma unroll
        for (int it = 0; it < 16; it++) {
            const int row = it * 8 + orow;
            uint32_t off = SWZ256((uint32_t)(row * 256 + ochk * 16));
            uint4 v = *(const uint4*)(smem + off);
            *(uint4*)((char*)(Y + (size_t)(m0 + row) * N + n0) + ochk * 16) = v;
        }
    } else {
        // ---- epilogue B: fused final layer: net += relu(acc+bias) . w3 ----
        // bias/w3 depend only on nt: hoist 32 loads out of the mt/h loops
        float bv0[8], bv1[8], wv0[8], wv1[8];
#pragma unroll
        for (int nt = 0; nt < 8; nt++) {
            const int col = n0 + ecol + nt * 8;
            bv0[nt] = __ldg(&bias[col]);
            bv1[nt] = __ldg(&bias[col + 1]);
            wv0[nt] = __ldg(&w3[col]);
            wv1[nt] = __ldg(&w3[col + 1]);
        }
#pragma unroll
        for (int mt = 0; mt < 4; mt++) {
#pragma unroll
            for (int h = 0; h < 2; h++) {
                float rs = 0.0f;
#pragma unroll
                for (int nt = 0; nt < 8; nt++) {
                    float v0 = fmaxf(acc[mt][nt][2 * h]     + bv0[nt], 0.0f);
                    float v1 = fmaxf(acc[mt][nt][2 * h + 1] + bv1[nt], 0.0f);
                    rs = fmaf(v0, wv0[nt], rs);
                    rs = fmaf(v1, wv1[nt], rs);
                }
                rs += __shfl_xor_sync(0xffffffffu, rs, 1);
                rs += __shfl_xor_sync(0xffffffffu, rs, 2);
                if ((lid & 3) == 0) {
                    const int row = m0 + erow + mt * 16 + h * 8;
                    atomicAdd(&net[row], rs);
                }
            }
        }
    }
}

// ---------------- scan: single launch, co-resident producer/consumer --------
// Blocks 0..63: compute chunk partials, signal counter.
// Blocks 64..127: hoist independent work, spin until all 64 partials done
// (all 128 blocks co-resident on 148 SMs -> forward progress guaranteed),
// then local fixup chain + replay. Arithmetic identical to R14's 2-kernel
// version. Counter reset by prep_kernel each replay.
__global__ void __launch_bounds__(256)
scan_kernel(const float* __restrict__ u, const float* __restrict__ pa,
            float* __restrict__ out) {
    const int b = threadIdx.x;
    const float a = *pa;

    if ((int)blockIdx.x < NCHUNK) {
        // ---- producer: chunk partial (chain of CLEN from 0) ----
        const int c = blockIdx.x;
        float y = 0.0f;
        const float* p = g_net + (size_t)c * CLEN * B_DIM + b;
#pragma unroll
        for (int j = 0; j < CLEN; j++) y = fmaf(a, y, p[j * B_DIM]);
        g_part[c * B_DIM + b] = y;
        __syncthreads();
        if (b == 0) { __threadfence(); atomicAdd(&g_scnt, 1); }
        return;
    }

    // ---- consumer: independent work first, then wait ----
    const int c = (int)blockIdx.x - NCHUNK;
    float aL = a;                     // a^CLEN by squaring (CLEN = 8)
    aL = aL * aL; aL = aL * aL; aL = aL * aL;
    float y0 = u[(size_t)b * F_DIM];  // u[0, b, 0]

    if (b == 0) {
        while (atomicAdd(&g_scnt, 0) < NCHUNK) __nanosleep(32);
        __threadfence();              // acquire
    }
    __syncthreads();

    // preload needed partials (coalesced, independent loads)
    float part[NCHUNK];
#pragma unroll
    for (int i = 0; i < NCHUNK; i++)
        part[i] = (i < c) ? g_part[i * B_DIM + b] : 0.0f;

    // local fixup chain: ystart_c (same op order as sequential fixup)
    float y = y0;
#pragma unroll
    for (int i = 0; i < NCHUNK; i++)
        if (i < c) y = fmaf(aL, y, part[i]);

    if (c == 0) out[b] = y;           // out[0, b] = y0
    const float* p = g_net + (size_t)c * CLEN * B_DIM + b;
    float* o = out + (size_t)(c * CLEN + 1) * B_DIM + b;
#pragma unroll
    for (int j = 0; j < CLEN; j++) {
        y = fmaf(a, y, p[j * B_DIM]);
        o[j * B_DIM] = y;
    }
}

// ---------------- launch ----------------
extern "C" void kernel_launch(void* const* d_in, const int* in_sizes, int n_in,
                              void* d_out, int out_size) {
    const float* u  = (const float*)d_in[0];
    const float* a  = (const float*)d_in[1];
    const float* b  = (const float*)d_in[2];
    const float* W0 = (const float*)d_in[3];
    const float* b0 = (const float*)d_in[4];
    const float* W1 = (const float*)d_in[5];
    const float* b1 = (const float*)d_in[6];
    const float* W2 = (const float*)d_in[7];
    const float* b2 = (const float*)d_in[8];
    const float* W3 = (const float*)d_in[9];
    const float* b3 = (const float*)d_in[10];
    float* out = (float*)d_out;

    void *pA, *pB, *pW0, *pW1, *pW2, *pNet;
    cudaGetSymbolAddress(&pA, g_A);   cudaGetSymbolAddress(&pB, g_B);
    cudaGetSymbolAddress(&pW0, g_W0); cudaGetSymbolAddress(&pW1, g_W1);
    cudaGetSymbolAddress(&pW2, g_W2); cudaGetSymbolAddress(&pNet, g_net);

    cudaFuncSetAttribute(gemm_kernel, cudaFuncAttributeMaxDynamicSharedMemorySize,
                         GEMM_SMEM);

    // 1. fused prep: pack + weight transposes + net init (+ scan counter reset)
    prep_kernel<<<NB_PREP, 256>>>(u, W0, W1, W2, b, b3);

    // 2. GEMMs: A(X0) -> B -> A -> net   (grid.x = N-tiles for A reuse in L2)
    dim3 grid(H_DIM / 128, M_ROWS / 128);
    gemm_kernel<<<grid, 128, GEMM_SMEM>>>(
        (const __half*)pA, (const __half*)pW0, b0, (__half*)pB, K0, H_DIM,
        nullptr, nullptr);
    gemm_kernel<<<grid, 128, GEMM_SMEM>>>(
        (const __half*)pB, (const __half*)pW1, b1, (__half*)pA, H_DIM, H_DIM,
        nullptr, nullptr);
    gemm_kernel<<<grid, 128, GEMM_SMEM>>>(
        (const __half*)pA, (const __half*)pW2, b2, (__half*)pB, H_DIM, H_DIM,
        W3, (float*)pNet);

    // 3. scan: one launch, producer/consumer blocks co-resident
    scan_kernel<<<2 * NCHUNK, B_DIM>>>(u, a, out);
}